// round 2
// baseline (speedup 1.0000x reference)
#include <cuda_runtime.h>
#include <math.h>

// ---------------------------------------------------------------------------
// QPNF RK45 on GB300 — fp32, warp-per-4-samples fused f(y) eval
// N=8192, D=32, M=8, H=128, MAX_STEPS=10, DT0=0.25
// ---------------------------------------------------------------------------

#define NN    8192
#define DD    32
#define HH    128
#define PITCH 36          // padded row (33 used cols)
#define NROW  (NN*PITCH)  // 294912

// gWeights layout (floats)
#define OFF_W1T   0        // [32][128]  W1T[j][a] = W1[a][j]
#define OFF_W2T   4096     // [128][128] W2T[a][b] = W2[b][a]
#define OFF_S     20480    // [128][128] S[a][b]
#define OFF_M     36864    // [128][32]  M[b][k]
#define OFF_P     40960    // [32][32]   P[j][k]
#define OFF_B1    41984    // [128]
#define OFF_B2    42112    // [128]
#define OFF_B3IP  42240    // [32]
#define OFF_TRP   42272    // [1] (+3 pad)
#define WTOTAL    42276
#define STAGE_FLOATS (16*640)          // 16 warps * 4 samples * (32 x + 128 h)
#define SMEM_FLOATS  (WTOTAL + STAGE_FLOATS)
#define SMEM_BYTES   (SMEM_FLOATS * 4) // 210,064 B

__device__ __align__(16) float gWeights[WTOTAL];
__device__ __align__(16) float gY [NROW];
__device__ __align__(16) float gY1[NROW];
__device__ __align__(16) float gK[7][NROW];
__device__ double gPartials[256];
__device__ float  g_t, g_dt, g_dtc, g_t1;
__device__ int    g_done, g_accept;

// RK45 (Dormand-Prince) stage coefficients
__constant__ float c_A[7][8] = {
  {0,0,0,0,0,0,0,0},
  {0.2f,0,0,0,0,0,0,0},
  {(float)(3.0/40.0),(float)(9.0/40.0),0,0,0,0,0,0},
  {(float)(44.0/45.0),(float)(-56.0/15.0),(float)(32.0/9.0),0,0,0,0,0},
  {(float)(19372.0/6561.0),(float)(-25360.0/2187.0),(float)(64448.0/6561.0),(float)(-212.0/729.0),0,0,0,0},
  {(float)(9017.0/3168.0),(float)(-355.0/33.0),(float)(46732.0/5247.0),(float)(49.0/176.0),(float)(-5103.0/18656.0),0,0,0},
  {0,0,0,0,0,0,0,0}
};
__constant__ int c_nt[7] = {0,1,2,3,4,5,0};

#define CB1 ((float)(35.0/384.0))
#define CB3 ((float)(500.0/1113.0))
#define CB4 ((float)(125.0/192.0))
#define CB5 ((float)(-2187.0/6784.0))
#define CB6 ((float)(11.0/84.0))
#define CE1 ((float)(35.0/384.0 - 5179.0/57600.0))
#define CE3 ((float)(500.0/1113.0 - 7571.0/16695.0))
#define CE4 ((float)(125.0/192.0 - 393.0/640.0))
#define CE5 ((float)(-2187.0/6784.0 + 92097.0/339200.0))
#define CE6 ((float)(11.0/84.0 - 187.0/2100.0))
#define CE7 ((float)(-1.0/40.0))

// ---------------------------------------------------------------------------
// Precompute (1 block, 128 threads): A^-1 G (fp64 LU), P, IP, M, S, transposes
// ---------------------------------------------------------------------------
__global__ void precompute_kernel(const float* __restrict__ G,
                                  const float* __restrict__ W1,
                                  const float* __restrict__ W2,
                                  const float* __restrict__ W3,
                                  const float* __restrict__ b1,
                                  const float* __restrict__ b2,
                                  const float* __restrict__ b3,
                                  const float* __restrict__ T)
{
    __shared__ double sA[8][8];
    __shared__ double sX[8][32];     // AinvG
    __shared__ float  sIP[32][32];
    __shared__ float  sT[32][128];   // IP @ W3
    int tid = threadIdx.x;

    if (tid < 64) {
        int i = tid >> 3, j = tid & 7;
        double a = 0;
        for (int k = 0; k < 32; k++) a += (double)G[i*32+k] * (double)G[j*32+k];
        sA[i][j] = a;
    }
    __syncthreads();

    if (tid == 0) {
        // Gauss-Jordan with partial pivoting, augmented [A | G]
        double M[8][40];
        for (int i = 0; i < 8; i++) {
            for (int j = 0; j < 8; j++)  M[i][j]   = sA[i][j];
            for (int c = 0; c < 32; c++) M[i][8+c] = (double)G[i*32+c];
        }
        for (int col = 0; col < 8; col++) {
            int p = col; double best = fabs(M[col][col]);
            for (int r = col+1; r < 8; r++) { double v = fabs(M[r][col]); if (v > best) { best = v; p = r; } }
            if (p != col) for (int c = 0; c < 40; c++) { double t = M[col][c]; M[col][c] = M[p][c]; M[p][c] = t; }
            double piv = M[col][col];
            for (int r = 0; r < 8; r++) {
                if (r == col) continue;
                double f = M[r][col] / piv;
                for (int c = col; c < 40; c++) M[r][c] -= f * M[col][c];
            }
        }
        for (int i = 0; i < 8; i++) {
            double d = M[i][i];
            for (int c = 0; c < 32; c++) sX[i][c] = M[i][8+c] / d;
        }
    }
    __syncthreads();

    // P[j][k], IP
    for (int idx = tid; idx < 1024; idx += 128) {
        int j = idx >> 5, k = idx & 31;
        double pv = 0;
        for (int i = 0; i < 8; i++) pv += (double)G[i*32+j] * sX[i][k];
        gWeights[OFF_P + idx] = (float)pv;
        sIP[j][k] = (float)(((j == k) ? 1.0 : 0.0) - pv);
    }
    __syncthreads();

    if (tid == 0) {
        double tr = 0;
        for (int j = 0; j < 32; j++) tr += (double)gWeights[OFF_P + j*32 + j];
        gWeights[OFF_TRP] = (float)tr;
        gWeights[OFF_TRP+1] = 0.f; gWeights[OFF_TRP+2] = 0.f; gWeights[OFF_TRP+3] = 0.f;
    }

    // M[b][k] = sum_j W3[j][b] * IP[j][k]
    for (int idx = tid; idx < 4096; idx += 128) {
        int b = idx >> 5, k = idx & 31;
        double m = 0;
        for (int j = 0; j < 32; j++) m += (double)W3[j*128+b] * (double)sIP[j][k];
        gWeights[OFF_M + idx] = (float)m;
    }
    // b3IP[k]
    if (tid < 32) {
        int k = tid; double v = 0;
        for (int j = 0; j < 32; j++) v += (double)b3[j] * (double)sIP[j][k];
        gWeights[OFF_B3IP + k] = (float)v;
    }
    // T[j][b] = sum_k IP[j][k] * W3[k][b]
    for (int idx = tid; idx < 4096; idx += 128) {
        int j = idx >> 7, b = idx & 127;
        double v = 0;
        for (int k = 0; k < 32; k++) v += (double)sIP[j][k] * (double)W3[k*128+b];
        sT[j][b] = (float)v;
    }
    __syncthreads();

    // S[a][b] = (sum_j W1[a][j] T[j][b]) * W2[b][a]
    for (int idx = tid; idx < 16384; idx += 128) {
        int a = idx >> 7, b = idx & 127;
        double e = 0;
        for (int j = 0; j < 32; j++) e += (double)W1[a*32+j] * (double)sT[j][b];
        gWeights[OFF_S + idx] = (float)(e * (double)W2[b*128+a]);
    }
    // W1T, W2T, biases
    for (int idx = tid; idx < 4096; idx += 128) {
        int j = idx >> 7, a = idx & 127;
        gWeights[OFF_W1T + idx] = W1[a*32+j];
    }
    for (int idx = tid; idx < 16384; idx += 128) {
        int a = idx >> 7, b = idx & 127;
        gWeights[OFF_W2T + idx] = W2[b*128+a];
    }
    for (int idx = tid; idx < 128; idx += 128) {
        gWeights[OFF_B1 + idx] = b1[idx];
        gWeights[OFF_B2 + idx] = b2[idx];
    }

    if (tid == 0) {
        float t1 = 2.0f * T[0];
        g_t1 = t1; g_t = 0.f; g_dt = 0.25f;
        int done = (0.f >= t1 - 1e-9f);
        g_done = done;
        g_dtc = done ? 1e-3f : fminf(0.25f, t1);
        g_accept = 0;
    }
}

// ---------------------------------------------------------------------------
__global__ void init_y_kernel(const float* __restrict__ z)
{
    int stride = gridDim.x * blockDim.x;
    for (int idx = blockIdx.x*blockDim.x + threadIdx.x; idx < NROW; idx += stride) {
        int n = idx / PITCH, c = idx - n*PITCH;
        gY[idx] = (c < 32) ? z[n*32 + c] : 0.f;
    }
}

// ---------------------------------------------------------------------------
// Fused f(y) evaluation. grid=128 blocks x 512 threads. warp -> 4 samples.
// ---------------------------------------------------------------------------
__global__ void __launch_bounds__(512, 1) eval_kernel(int stage)
{
    extern __shared__ float sm[];
    {   // cooperative weight stage: 42276 floats, float4
        float4* dst = (float4*)sm;
        const float4* src = (const float4*)gWeights;
        for (int i = threadIdx.x; i < WTOTAL/4; i += 512) dst[i] = src[i];
    }
    __syncthreads();

    const float* sW1T  = sm + OFF_W1T;
    const float* sW2T  = sm + OFF_W2T;
    const float* sS    = sm + OFF_S;
    const float* sM    = sm + OFF_M;
    const float* sP    = sm + OFF_P;
    const float* sB1   = sm + OFF_B1;
    const float* sB2   = sm + OFF_B2;
    const float* sB3IP = sm + OFF_B3IP;
    float trP = sm[OFF_TRP];

    int warp = threadIdx.x >> 5, lane = threadIdx.x & 31;
    float* xs = sm + WTOTAL + warp*640;  // [s*160 + j], h at +32
    int n0 = blockIdx.x*64 + warp*4;
    float dtc = g_dtc;
    const float* yb = (stage == 6) ? gY1 : gY;
    int nt = c_nt[stage];

    // ---- form x ----
    for (int s = 0; s < 4; s++) {
        int r = (n0+s)*PITCH;
        float acc = 0.f;
        for (int m = 0; m < nt; m++) acc += c_A[stage][m] * gK[m][r+lane];
        xs[s*160 + lane] = yb[r+lane] + dtc*acc;
    }
    __syncwarp();

    // ---- layer 1: pre1 = W1 x + b1 ; h1 = relu ----
    float p1[4][4];
    #pragma unroll
    for (int s = 0; s < 4; s++) { p1[s][0]=0; p1[s][1]=0; p1[s][2]=0; p1[s][3]=0; }
    #pragma unroll 4
    for (int j = 0; j < 32; j++) {
        float4 w = *(const float4*)(sW1T + j*128 + 4*lane);
        #pragma unroll
        for (int s = 0; s < 4; s++) {
            float xv = xs[s*160 + j];
            p1[s][0] += w.x*xv; p1[s][1] += w.y*xv; p1[s][2] += w.z*xv; p1[s][3] += w.w*xv;
        }
    }
    {
        float4 bv = *(const float4*)(sB1 + 4*lane);
        #pragma unroll
        for (int s = 0; s < 4; s++) {
            float4 h;
            h.x = fmaxf(p1[s][0]+bv.x, 0.f); h.y = fmaxf(p1[s][1]+bv.y, 0.f);
            h.z = fmaxf(p1[s][2]+bv.z, 0.f); h.w = fmaxf(p1[s][3]+bv.w, 0.f);
            *(float4*)(xs + s*160 + 32 + 4*lane) = h;
        }
    }
    __syncwarp();

    // ---- layer 2 + S-bilinear: pre2 = W2 h1 + b2 ; r = S^T m1 ----
    float aP[4][4], aR[4][4];
    #pragma unroll
    for (int s = 0; s < 4; s++)
        #pragma unroll
        for (int i = 0; i < 4; i++) { aP[s][i]=0.f; aR[s][i]=0.f; }
    #pragma unroll 2
    for (int a = 0; a < 128; a++) {
        float4 w  = *(const float4*)(sW2T + a*128 + 4*lane);
        float4 sv = *(const float4*)(sS   + a*128 + 4*lane);
        #pragma unroll
        for (int s = 0; s < 4; s++) {
            float ha = xs[s*160 + 32 + a];
            float ma = (ha > 0.f) ? 1.f : 0.f;
            aP[s][0] += w.x*ha;  aP[s][1] += w.y*ha;  aP[s][2] += w.z*ha;  aP[s][3] += w.w*ha;
            aR[s][0] += sv.x*ma; aR[s][1] += sv.y*ma; aR[s][2] += sv.z*ma; aR[s][3] += sv.w*ma;
        }
    }
    float h2[4][4], dlp[4];
    {
        float4 bv = *(const float4*)(sB2 + 4*lane);
        #pragma unroll
        for (int s = 0; s < 4; s++) {
            dlp[s] = 0.f;
            float pre;
            pre = aP[s][0]+bv.x; h2[s][0] = fmaxf(pre,0.f); if (pre > 0.f) dlp[s] += aR[s][0];
            pre = aP[s][1]+bv.y; h2[s][1] = fmaxf(pre,0.f); if (pre > 0.f) dlp[s] += aR[s][1];
            pre = aP[s][2]+bv.z; h2[s][2] = fmaxf(pre,0.f); if (pre > 0.f) dlp[s] += aR[s][2];
            pre = aP[s][3]+bv.w; h2[s][3] = fmaxf(pre,0.f); if (pre > 0.f) dlp[s] += aR[s][3];
        }
    }
    __syncwarp();   // all h1 reads done before overwrite
    #pragma unroll
    for (int s = 0; s < 4; s++) {
        float4 h; h.x=h2[s][0]; h.y=h2[s][1]; h.z=h2[s][2]; h.w=h2[s][3];
        *(float4*)(xs + s*160 + 32 + 4*lane) = h;
    }
    __syncwarp();

    // ---- dlogp = m1^T S m2 + trP ----
    #pragma unroll
    for (int s = 0; s < 4; s++) {
        float v = dlp[s];
        for (int o = 16; o > 0; o >>= 1) v += __shfl_xor_sync(0xffffffffu, v, o);
        if (lane == 0) gK[stage][(n0+s)*PITCH + 32] = v + trP;
    }

    // ---- dz = -h2 M - b3IP - x P ----
    float acc3[4];
    #pragma unroll
    for (int s = 0; s < 4; s++) acc3[s] = -sB3IP[lane];
    #pragma unroll 2
    for (int b = 0; b < 128; b++) {
        float m = sM[b*32 + lane];
        #pragma unroll
        for (int s = 0; s < 4; s++) acc3[s] -= xs[s*160 + 32 + b] * m;
    }
    #pragma unroll 2
    for (int j = 0; j < 32; j++) {
        float pv = sP[j*32 + lane];
        #pragma unroll
        for (int s = 0; s < 4; s++) acc3[s] -= xs[s*160 + j] * pv;
    }
    #pragma unroll
    for (int s = 0; s < 4; s++) gK[stage][(n0+s)*PITCH + lane] = acc3[s];
}

// ---------------------------------------------------------------------------
__global__ void combine_y1_kernel()
{
    float dtc = g_dtc;
    int stride = gridDim.x * blockDim.x;
    for (int idx = blockIdx.x*blockDim.x + threadIdx.x; idx < NN*33; idx += stride) {
        int n = idx / 33, c = idx - n*33, r = n*PITCH + c;
        float acc = CB1*gK[0][r] + CB3*gK[2][r] + CB4*gK[3][r] + CB5*gK[4][r] + CB6*gK[5][r];
        gY1[r] = gY[r] + dtc*acc;
    }
}

__global__ void reduce_kernel()
{
    float dtc = g_dtc;
    double lsum = 0;
    int stride = gridDim.x * blockDim.x;
    for (int idx = blockIdx.x*blockDim.x + threadIdx.x; idx < NN*33; idx += stride) {
        int n = idx / 33, c = idx - n*33, r = n*PITCH + c;
        float ev = dtc*( CE1*gK[0][r] + CE3*gK[2][r] + CE4*gK[3][r]
                       + CE5*gK[4][r] + CE6*gK[5][r] + CE7*gK[6][r] );
        float tol = 1e-5f + 1e-5f * fmaxf(fabsf(gY[r]), fabsf(gY1[r]));
        float q = ev / tol;
        lsum += (double)(q*q);
    }
    __shared__ double red[256];
    int tid = threadIdx.x;
    red[tid] = lsum; __syncthreads();
    for (int s = 128; s > 0; s >>= 1) { if (tid < s) red[tid] += red[tid+s]; __syncthreads(); }
    if (tid == 0) gPartials[blockIdx.x] = red[0];
}

__global__ void control_kernel()
{
    __shared__ double red[256];
    int tid = threadIdx.x;
    red[tid] = gPartials[tid]; __syncthreads();
    for (int s = 128; s > 0; s >>= 1) { if (tid < s) red[tid] += red[tid+s]; __syncthreads(); }
    if (tid == 0) {
        float errn = sqrtf((float)(red[0] / (8192.0*33.0)));
        int done = g_done;
        int accept = (!done) && (errn <= 1.0f);
        g_accept = accept;
        float t = g_t, dt = g_dt, dtc = g_dtc, t1 = g_t1;
        if (accept) t += dtc;
        float factor = 0.9f * powf(errn, -0.2f);
        factor = fminf(fmaxf(factor, 0.2f), 10.0f);
        float dtn = done ? dt : fminf(fmaxf(dtc*factor, 1e-6f), t1);
        g_t = t; g_dt = dtn;
        int done2 = (t >= t1 - 1e-9f);
        g_done = done2;
        g_dtc = done2 ? 1e-3f : fminf(dtn, t1 - t);
    }
}

__global__ void update_y_kernel()
{
    if (!g_accept) return;
    int stride = gridDim.x * blockDim.x;
    for (int idx = blockIdx.x*blockDim.x + threadIdx.x; idx < NROW; idx += stride)
        gY[idx] = gY1[idx];
}

__global__ void writeout_kernel(float* __restrict__ out)
{
    int stride = gridDim.x * blockDim.x;
    for (int idx = blockIdx.x*blockDim.x + threadIdx.x; idx < NN*32; idx += stride) {
        int n = idx >> 5, j = idx & 31;
        out[idx] = gY[n*PITCH + j];
    }
}

// ---------------------------------------------------------------------------
extern "C" void kernel_launch(void* const* d_in, const int* in_sizes, int n_in,
                              void* d_out, int out_size)
{
    const float* z   = (const float*)d_in[0];
    const float* G   = (const float*)d_in[1];
    const float* W1  = (const float*)d_in[2];
    const float* b1  = (const float*)d_in[3];
    const float* W2  = (const float*)d_in[4];
    const float* b2  = (const float*)d_in[5];
    const float* W3  = (const float*)d_in[6];
    const float* b3  = (const float*)d_in[7];
    const float* T   = (const float*)d_in[8];

    cudaFuncSetAttribute(eval_kernel, cudaFuncAttributeMaxDynamicSharedMemorySize, SMEM_BYTES);

    precompute_kernel<<<1, 128>>>(G, W1, W2, W3, b1, b2, b3, T);
    init_y_kernel<<<256, 256>>>(z);

    for (int step = 0; step < 10; step++) {
        for (int st = 0; st < 6; st++)
            eval_kernel<<<128, 512, SMEM_BYTES>>>(st);
        combine_y1_kernel<<<264, 256>>>();
        eval_kernel<<<128, 512, SMEM_BYTES>>>(6);   // k7 from y1
        reduce_kernel<<<256, 256>>>();
        control_kernel<<<1, 256>>>();
        update_y_kernel<<<288, 256>>>();
    }
    writeout_kernel<<<256, 256>>>((float*)d_out);
}

// round 4
// speedup vs baseline: 1.2350x; 1.2350x over previous
#include <cuda_runtime.h>
#include <math.h>

typedef unsigned long long ull;

// ---------------------------------------------------------------------------
// QPNF RK45 on GB300 — persistent per-step kernel, f32x2 packed FMA
// N=8192, D=32, M=8, H=128, MAX_STEPS=10, DT0=0.25
// ---------------------------------------------------------------------------

#define NN    8192
#define NWARP 16
#define BLK   512
#define GRID  128

// weight blob offsets (floats)
#define OFF_W1T   0        // [32][128]  W1T[j][a] = W1[a][j]
#define OFF_W2T   4096     // [128][128] W2T[a][b] = W2[b][a]
#define OFF_S     20480    // [128][128] S[a][b]
#define OFF_B1    36864    // [128]
#define OFF_B2    36992    // [128]
#define OFF_B3IP  37120    // [32]
#define OFF_TRP   37152    // [1] (+3 pad)
#define WTOT      37156
#define PW        1216     // per-warp stage floats
#define SMEM_FLOATS (WTOT + NWARP*PW)
#define SMEM_BYTES  (SMEM_FLOATS*4)   // 226,448 B

__device__ __align__(16) float gW[WTOT];
__device__ __align__(16) float gM[4096];   // M[b*32+k]
__device__ __align__(16) float gP[1024];   // P[j*32+k]
__device__ __align__(16) float gYbuf[2][NN*33];
__device__ double gErr;
__device__ float  g_t, g_dt, g_dtc, g_t1;
__device__ int    g_done, g_cur;

__constant__ float c_A[7][5] = {
  {0,0,0,0,0},
  {0.2f,0,0,0,0},
  {(float)(3.0/40.0),(float)(9.0/40.0),0,0,0},
  {(float)(44.0/45.0),(float)(-56.0/15.0),(float)(32.0/9.0),0,0},
  {(float)(19372.0/6561.0),(float)(-25360.0/2187.0),(float)(64448.0/6561.0),(float)(-212.0/729.0),0},
  {(float)(9017.0/3168.0),(float)(-355.0/33.0),(float)(46732.0/5247.0),(float)(49.0/176.0),(float)(-5103.0/18656.0)},
  {0,0,0,0,0}
};

#define CB1 ((float)(35.0/384.0))
#define CB3 ((float)(500.0/1113.0))
#define CB4 ((float)(125.0/192.0))
#define CB5 ((float)(-2187.0/6784.0))
#define CB6 ((float)(11.0/84.0))
#define CE1 ((float)(35.0/384.0 - 5179.0/57600.0))
#define CE3 ((float)(500.0/1113.0 - 7571.0/16695.0))
#define CE4 ((float)(125.0/192.0 - 393.0/640.0))
#define CE5 ((float)(-2187.0/6784.0 + 92097.0/339200.0))
#define CE6 ((float)(11.0/84.0 - 187.0/2100.0))
#define CE7 ((float)(-1.0/40.0))

#define PACKF(d,x,y)   asm volatile("mov.b64 %0, {%1, %2};" : "=l"(d) : "f"(x), "f"(y))
#define UNPACKF(x,y,d) asm volatile("mov.b64 {%0, %1}, %2;" : "=f"(x), "=f"(y) : "l"(d))
#define FMA2(d,a,b)    asm volatile("fma.rn.f32x2 %0, %1, %2, %0;" : "+l"(d) : "l"(a), "l"(b))

// ---------------------------------------------------------------------------
// Precompute: A^-1 G (fp64), P, IP, M, S, transposes into gW/gM/gP + scalars
// ---------------------------------------------------------------------------
__global__ void precompute_kernel(const float* __restrict__ G,
                                  const float* __restrict__ W1,
                                  const float* __restrict__ W2,
                                  const float* __restrict__ W3,
                                  const float* __restrict__ b1,
                                  const float* __restrict__ b2,
                                  const float* __restrict__ b3,
                                  const float* __restrict__ T)
{
    __shared__ double sA[8][8];
    __shared__ double sX[8][32];     // AinvG
    __shared__ float  sIP[32][32];
    __shared__ float  sT[32][128];   // IP @ W3
    int tid = threadIdx.x;

    if (tid < 64) {
        int i = tid >> 3, j = tid & 7;
        double a = 0;
        for (int k = 0; k < 32; k++) a += (double)G[i*32+k] * (double)G[j*32+k];
        sA[i][j] = a;
    }
    __syncthreads();

    if (tid == 0) {
        double M[8][40];
        for (int i = 0; i < 8; i++) {
            for (int j = 0; j < 8; j++)  M[i][j]   = sA[i][j];
            for (int c = 0; c < 32; c++) M[i][8+c] = (double)G[i*32+c];
        }
        for (int col = 0; col < 8; col++) {
            int p = col; double best = fabs(M[col][col]);
            for (int r = col+1; r < 8; r++) { double v = fabs(M[r][col]); if (v > best) { best = v; p = r; } }
            if (p != col) for (int c = 0; c < 40; c++) { double t = M[col][c]; M[col][c] = M[p][c]; M[p][c] = t; }
            double piv = M[col][col];
            for (int r = 0; r < 8; r++) {
                if (r == col) continue;
                double f = M[r][col] / piv;
                for (int c = col; c < 40; c++) M[r][c] -= f * M[col][c];
            }
        }
        for (int i = 0; i < 8; i++) {
            double d = M[i][i];
            for (int c = 0; c < 32; c++) sX[i][c] = M[i][8+c] / d;
        }
    }
    __syncthreads();

    // P, IP
    for (int idx = tid; idx < 1024; idx += 128) {
        int j = idx >> 5, k = idx & 31;
        double pv = 0;
        for (int i = 0; i < 8; i++) pv += (double)G[i*32+j] * sX[i][k];
        gP[idx] = (float)pv;
        sIP[j][k] = (float)(((j == k) ? 1.0 : 0.0) - pv);
    }
    __syncthreads();

    if (tid == 0) {
        double tr = 0;
        for (int j = 0; j < 32; j++) tr += (double)gP[j*32 + j];
        gW[OFF_TRP] = (float)tr;
        gW[OFF_TRP+1] = 0.f; gW[OFF_TRP+2] = 0.f; gW[OFF_TRP+3] = 0.f;
    }

    // M[b][k] = sum_j W3[j][b] * IP[j][k]
    for (int idx = tid; idx < 4096; idx += 128) {
        int b = idx >> 5, k = idx & 31;
        double m = 0;
        for (int j = 0; j < 32; j++) m += (double)W3[j*128+b] * (double)sIP[j][k];
        gM[idx] = (float)m;
    }
    // b3IP
    if (tid < 32) {
        int k = tid; double v = 0;
        for (int j = 0; j < 32; j++) v += (double)b3[j] * (double)sIP[j][k];
        gW[OFF_B3IP + k] = (float)v;
    }
    // T[j][b] = sum_k IP[j][k] * W3[k][b]
    for (int idx = tid; idx < 4096; idx += 128) {
        int j = idx >> 7, b = idx & 127;
        double v = 0;
        for (int k = 0; k < 32; k++) v += (double)sIP[j][k] * (double)W3[k*128+b];
        sT[j][b] = (float)v;
    }
    __syncthreads();

    // S[a][b] = (sum_j W1[a][j] T[j][b]) * W2[b][a]
    for (int idx = tid; idx < 16384; idx += 128) {
        int a = idx >> 7, b = idx & 127;
        double e = 0;
        for (int j = 0; j < 32; j++) e += (double)W1[a*32+j] * (double)sT[j][b];
        gW[OFF_S + idx] = (float)(e * (double)W2[b*128+a]);
    }
    // W1T, W2T, biases
    for (int idx = tid; idx < 4096; idx += 128) {
        int j = idx >> 7, a = idx & 127;
        gW[OFF_W1T + idx] = W1[a*32+j];
    }
    for (int idx = tid; idx < 16384; idx += 128) {
        int a = idx >> 7, b = idx & 127;
        gW[OFF_W2T + idx] = W2[b*128+a];
    }
    if (tid < 128) {
        gW[OFF_B1 + tid] = b1[tid];
        gW[OFF_B2 + tid] = b2[tid];
    }

    if (tid == 0) {
        float t1 = 2.0f * T[0];
        g_t1 = t1; g_t = 0.f; g_dt = 0.25f;
        int done = (0.f >= t1 - 1e-9f);
        g_done = done;
        g_dtc = done ? 1e-3f : fminf(0.25f, t1);
        g_cur = 0;
        gErr = 0.0;
    }
}

// ---------------------------------------------------------------------------
__global__ void init_y_kernel(const float* __restrict__ z)
{
    int stride = gridDim.x * blockDim.x;
    for (int idx = blockIdx.x*blockDim.x + threadIdx.x; idx < NN*33; idx += stride) {
        int n = idx / 33, c = idx - n*33;
        gYbuf[0][idx] = (c < 32) ? z[n*32 + c] : 0.f;
    }
}

// ---------------------------------------------------------------------------
// One full RK45 step (all 7 stages) per launch. warp -> 4 samples.
// ---------------------------------------------------------------------------
__global__ void __launch_bounds__(BLK, 1) step_kernel()
{
    extern __shared__ float sm[];
    {   // stage weights once per step
        float4* dst = (float4*)sm;
        const float4* src = (const float4*)gW;
        for (int i = threadIdx.x; i < WTOT/4; i += BLK) dst[i] = src[i];
    }
    __syncthreads();

    const float* sW1T  = sm + OFF_W1T;
    const float* sW2T  = sm + OFF_W2T;
    const float* sS    = sm + OFF_S;
    const float* sB1   = sm + OFF_B1;
    const float* sB2   = sm + OFF_B2;
    const float* sB3IP = sm + OFF_B3IP;
    const float  trP   = sm[OFF_TRP];

    const int warp = threadIdx.x >> 5, lane = threadIdx.x & 31;
    float* ws    = sm + WTOT + warp*PW;
    float* sXP01 = ws;          // 32 pairs (64 fl)
    float* sXP23 = ws + 64;
    float* sHP01 = ws + 128;    // 128 pairs (256 fl)
    float* sHP23 = ws + 384;
    float* sMP01 = ws + 640;
    float* sMP23 = ws + 896;
    float* sKDL  = ws + 1152;   // [m*4+s], 28 fl

    const float dtc = g_dtc;
    const int   cur = g_cur;
    const float* __restrict__ Y  = gYbuf[cur];
    float* __restrict__       Y1 = gYbuf[cur ^ 1];
    const int n0 = blockIdx.x*64 + warp*4;

    float yr[4], y1r[4], y32[4], y132[4];
    #pragma unroll
    for (int s = 0; s < 4; s++) { yr[s] = Y[(n0+s)*33 + lane]; y1r[s] = 0.f; y132[s] = 0.f; y32[s] = 0.f; }
    if (lane == 0) {
        #pragma unroll
        for (int s = 0; s < 4; s++) y32[s] = Y[(n0+s)*33 + 32];
    }

    float k0[4],k1[4],k2[4],k3[4],k4[4],k5[4];
    #pragma unroll
    for (int s = 0; s < 4; s++) { k0[s]=0;k1[s]=0;k2[s]=0;k3[s]=0;k4[s]=0;k5[s]=0; }
    float lsum = 0.f;

    #pragma unroll 1
    for (int m = 0; m < 7; m++) {
        const float a0=c_A[m][0], a1=c_A[m][1], a2=c_A[m][2], a3=c_A[m][3], a4=c_A[m][4];

        __syncwarp();   // previous stage's XP readers done
        // ---- form x, write sample-pair arrays ----
        {
            float xv[4];
            #pragma unroll
            for (int s = 0; s < 4; s++) {
                float base = (m == 6) ? y1r[s] : yr[s];
                float acc = a0*k0[s] + a1*k1[s] + a2*k2[s] + a3*k3[s] + a4*k4[s];
                xv[s] = fmaf(dtc, acc, base);
            }
            ull p01, p23;
            PACKF(p01, xv[0], xv[1]); PACKF(p23, xv[2], xv[3]);
            *(ull*)(sXP01 + 2*lane) = p01;
            *(ull*)(sXP23 + 2*lane) = p23;
        }
        __syncwarp();

        // ---- layer 1: pre1 = W1 x ----
        ull A01[4], A23[4];
        #pragma unroll
        for (int i = 0; i < 4; i++) { A01[i] = 0ull; A23[i] = 0ull; }
        #pragma unroll 4
        for (int j = 0; j < 32; j++) {
            float4 w  = *(const float4*)(sW1T + j*128 + 4*lane);
            ull x01 = *(const ull*)(sXP01 + 2*j);
            ull x23 = *(const ull*)(sXP23 + 2*j);
            ull t;
            PACKF(t, w.x, w.x); FMA2(A01[0], t, x01); FMA2(A23[0], t, x23);
            PACKF(t, w.y, w.y); FMA2(A01[1], t, x01); FMA2(A23[1], t, x23);
            PACKF(t, w.z, w.z); FMA2(A01[2], t, x01); FMA2(A23[2], t, x23);
            PACKF(t, w.w, w.w); FMA2(A01[3], t, x01); FMA2(A23[3], t, x23);
        }
        // relu + masks -> HP/MP pair arrays
        {
            float4 bv = *(const float4*)(sB1 + 4*lane);
            float bb[4] = {bv.x, bv.y, bv.z, bv.w};
            #pragma unroll
            for (int i = 0; i < 4; i++) {
                float p0,p1,p2,p3;
                UNPACKF(p0, p1, A01[i]); UNPACKF(p2, p3, A23[i]);
                p0 += bb[i]; p1 += bb[i]; p2 += bb[i]; p3 += bb[i];
                ull hp, mp;
                PACKF(hp, fmaxf(p0,0.f), fmaxf(p1,0.f));
                PACKF(mp, (p0>0.f)?1.f:0.f, (p1>0.f)?1.f:0.f);
                *(ull*)(sHP01 + 2*(4*lane+i)) = hp;
                *(ull*)(sMP01 + 2*(4*lane+i)) = mp;
                PACKF(hp, fmaxf(p2,0.f), fmaxf(p3,0.f));
                PACKF(mp, (p2>0.f)?1.f:0.f, (p3>0.f)?1.f:0.f);
                *(ull*)(sHP23 + 2*(4*lane+i)) = hp;
                *(ull*)(sMP23 + 2*(4*lane+i)) = mp;
            }
        }
        __syncwarp();

        // ---- layer 2 + S-bilinear ----
        ull P01[4],P23[4],R01[4],R23[4];
        #pragma unroll
        for (int i = 0; i < 4; i++) { P01[i]=0ull; P23[i]=0ull; R01[i]=0ull; R23[i]=0ull; }
        #pragma unroll 2
        for (int a = 0; a < 128; a++) {
            float4 w  = *(const float4*)(sW2T + a*128 + 4*lane);
            float4 sv = *(const float4*)(sS   + a*128 + 4*lane);
            ull h01 = *(const ull*)(sHP01 + 2*a);
            ull h23 = *(const ull*)(sHP23 + 2*a);
            ull m01 = *(const ull*)(sMP01 + 2*a);
            ull m23 = *(const ull*)(sMP23 + 2*a);
            ull t;
            PACKF(t, w.x,  w.x ); FMA2(P01[0], t, h01); FMA2(P23[0], t, h23);
            PACKF(t, w.y,  w.y ); FMA2(P01[1], t, h01); FMA2(P23[1], t, h23);
            PACKF(t, w.z,  w.z ); FMA2(P01[2], t, h01); FMA2(P23[2], t, h23);
            PACKF(t, w.w,  w.w ); FMA2(P01[3], t, h01); FMA2(P23[3], t, h23);
            PACKF(t, sv.x, sv.x); FMA2(R01[0], t, m01); FMA2(R23[0], t, m23);
            PACKF(t, sv.y, sv.y); FMA2(R01[1], t, m01); FMA2(R23[1], t, m23);
            PACKF(t, sv.z, sv.z); FMA2(R01[2], t, m01); FMA2(R23[2], t, m23);
            PACKF(t, sv.w, sv.w); FMA2(R01[3], t, m01); FMA2(R23[3], t, m23);
        }
        __syncwarp();   // layer-2 reads done before HP overwrite

        // ---- h2 + dlp partials; write h2 pairs into HP arrays ----
        float dlp[4] = {0.f, 0.f, 0.f, 0.f};
        {
            float4 bv = *(const float4*)(sB2 + 4*lane);
            float bb[4] = {bv.x, bv.y, bv.z, bv.w};
            #pragma unroll
            for (int i = 0; i < 4; i++) {
                float p0,p1,p2,p3, r0,r1,r2,r3;
                UNPACKF(p0, p1, P01[i]); UNPACKF(p2, p3, P23[i]);
                UNPACKF(r0, r1, R01[i]); UNPACKF(r2, r3, R23[i]);
                p0 += bb[i]; p1 += bb[i]; p2 += bb[i]; p3 += bb[i];
                if (p0 > 0.f) dlp[0] += r0;
                if (p1 > 0.f) dlp[1] += r1;
                if (p2 > 0.f) dlp[2] += r2;
                if (p3 > 0.f) dlp[3] += r3;
                ull hp;
                PACKF(hp, fmaxf(p0,0.f), fmaxf(p1,0.f));
                *(ull*)(sHP01 + 2*(4*lane+i)) = hp;
                PACKF(hp, fmaxf(p2,0.f), fmaxf(p3,0.f));
                *(ull*)(sHP23 + 2*(4*lane+i)) = hp;
            }
        }
        __syncwarp();

        // ---- dlp warp reduction (result on all lanes) ----
        #pragma unroll
        for (int s = 0; s < 4; s++) {
            float v = dlp[s];
            v += __shfl_xor_sync(0xffffffffu, v, 16);
            v += __shfl_xor_sync(0xffffffffu, v, 8);
            v += __shfl_xor_sync(0xffffffffu, v, 4);
            v += __shfl_xor_sync(0xffffffffu, v, 2);
            v += __shfl_xor_sync(0xffffffffu, v, 1);
            dlp[s] = v + trP;
        }
        if (lane == 0) {
            #pragma unroll
            for (int s = 0; s < 4; s++) sKDL[m*4 + s] = dlp[s];
        }

        // ---- dz = -(h2 M + x P + b3IP) ----
        ull D01, D23;
        {
            float bi = sB3IP[lane];
            PACKF(D01, bi, bi); PACKF(D23, bi, bi);
        }
        #pragma unroll 8
        for (int b = 0; b < 128; b++) {
            float mv = gM[b*32 + lane];
            ull t; PACKF(t, mv, mv);
            FMA2(D01, t, *(const ull*)(sHP01 + 2*b));
            FMA2(D23, t, *(const ull*)(sHP23 + 2*b));
        }
        #pragma unroll 8
        for (int j = 0; j < 32; j++) {
            float pv = gP[j*32 + lane];
            ull t; PACKF(t, pv, pv);
            FMA2(D01, t, *(const ull*)(sXP01 + 2*j));
            FMA2(D23, t, *(const ull*)(sXP23 + 2*j));
        }
        float kv[4];
        {
            float d0,d1,d2,d3;
            UNPACKF(d0, d1, D01); UNPACKF(d2, d3, D23);
            kv[0] = -d0; kv[1] = -d1; kv[2] = -d2; kv[3] = -d3;
        }

        if (m == 0)      { k0[0]=kv[0];k0[1]=kv[1];k0[2]=kv[2];k0[3]=kv[3]; }
        else if (m == 1) { k1[0]=kv[0];k1[1]=kv[1];k1[2]=kv[2];k1[3]=kv[3]; }
        else if (m == 2) { k2[0]=kv[0];k2[1]=kv[1];k2[2]=kv[2];k2[3]=kv[3]; }
        else if (m == 3) { k3[0]=kv[0];k3[1]=kv[1];k3[2]=kv[2];k3[3]=kv[3]; }
        else if (m == 4) { k4[0]=kv[0];k4[1]=kv[1];k4[2]=kv[2];k4[3]=kv[3]; }
        else if (m == 5) { k5[0]=kv[0];k5[1]=kv[1];k5[2]=kv[2];k5[3]=kv[3]; }

        if (m == 5) {   // y1 (5th-order solution)
            #pragma unroll
            for (int s = 0; s < 4; s++) {
                float acc = CB1*k0[s] + CB3*k2[s] + CB4*k3[s] + CB5*k4[s] + CB6*k5[s];
                y1r[s] = fmaf(dtc, acc, yr[s]);
                Y1[(n0+s)*33 + lane] = y1r[s];
            }
            if (lane == 0) {
                #pragma unroll
                for (int s = 0; s < 4; s++) {
                    float acc = CB1*sKDL[0*4+s] + CB3*sKDL[2*4+s] + CB4*sKDL[3*4+s]
                              + CB5*sKDL[4*4+s] + CB6*sKDL[5*4+s];
                    y132[s] = fmaf(dtc, acc, y32[s]);
                    Y1[(n0+s)*33 + 32] = y132[s];
                }
            }
        }
        if (m == 6) {   // error contributions
            #pragma unroll
            for (int s = 0; s < 4; s++) {
                float ev = dtc*(CE1*k0[s] + CE3*k2[s] + CE4*k3[s]
                              + CE5*k4[s] + CE6*k5[s] + CE7*kv[s]);
                float tol = 1e-5f + 1e-5f*fmaxf(fabsf(yr[s]), fabsf(y1r[s]));
                float q = ev / tol;
                lsum += q*q;
            }
            if (lane == 0) {
                #pragma unroll
                for (int s = 0; s < 4; s++) {
                    float ev = dtc*(CE1*sKDL[0*4+s] + CE3*sKDL[2*4+s] + CE4*sKDL[3*4+s]
                                  + CE5*sKDL[4*4+s] + CE6*sKDL[5*4+s] + CE7*dlp[s]);
                    float tol = 1e-5f + 1e-5f*fmaxf(fabsf(y32[s]), fabsf(y132[s]));
                    float q = ev / tol;
                    lsum += q*q;
                }
            }
        }
    }

    // ---- block error reduction -> one atomic ----
    {
        float v = lsum;
        v += __shfl_xor_sync(0xffffffffu, v, 16);
        v += __shfl_xor_sync(0xffffffffu, v, 8);
        v += __shfl_xor_sync(0xffffffffu, v, 4);
        v += __shfl_xor_sync(0xffffffffu, v, 2);
        v += __shfl_xor_sync(0xffffffffu, v, 1);
        if (lane == 0) *(double*)(ws + 1184) = (double)v;
    }
    __syncthreads();
    if (threadIdx.x == 0) {
        double tot = 0.0;
        for (int w = 0; w < NWARP; w++)
            tot += *(const double*)(sm + WTOT + w*PW + 1184);
        atomicAdd(&gErr, tot);
    }
}

// ---------------------------------------------------------------------------
__global__ void control_kernel()
{
    double sum = gErr;
    gErr = 0.0;
    float errn = sqrtf((float)(sum / (8192.0*33.0)));
    int done = g_done;
    int accept = (!done) && (errn <= 1.0f);
    float t = g_t, dt = g_dt, dtc = g_dtc, t1 = g_t1;
    if (accept) { t += dtc; g_cur ^= 1; }
    float factor = fminf(fmaxf(0.9f * powf(errn, -0.2f), 0.2f), 10.0f);
    float dtn = done ? dt : fminf(fmaxf(dtc*factor, 1e-6f), t1);
    g_t = t; g_dt = dtn;
    int done2 = (t >= t1 - 1e-9f);
    g_done = done2;
    g_dtc = done2 ? 1e-3f : fminf(dtn, t1 - t);
}

__global__ void writeout_kernel(float* __restrict__ out)
{
    const float* Y = gYbuf[g_cur];
    int stride = gridDim.x * blockDim.x;
    for (int idx = blockIdx.x*blockDim.x + threadIdx.x; idx < NN*32; idx += stride) {
        int n = idx >> 5, j = idx & 31;
        out[idx] = Y[n*33 + j];
    }
}

// ---------------------------------------------------------------------------
extern "C" void kernel_launch(void* const* d_in, const int* in_sizes, int n_in,
                              void* d_out, int out_size)
{
    const float* z   = (const float*)d_in[0];
    const float* G   = (const float*)d_in[1];
    const float* W1  = (const float*)d_in[2];
    const float* b1  = (const float*)d_in[3];
    const float* W2  = (const float*)d_in[4];
    const float* b2  = (const float*)d_in[5];
    const float* W3  = (const float*)d_in[6];
    const float* b3  = (const float*)d_in[7];
    const float* T   = (const float*)d_in[8];

    cudaFuncSetAttribute(step_kernel, cudaFuncAttributeMaxDynamicSharedMemorySize, SMEM_BYTES);

    precompute_kernel<<<1, 128>>>(G, W1, W2, W3, b1, b2, b3, T);
    init_y_kernel<<<256, 256>>>(z);

    for (int step = 0; step < 10; step++) {
        step_kernel<<<GRID, BLK, SMEM_BYTES>>>();
        control_kernel<<<1, 1>>>();
    }
    writeout_kernel<<<256, 256>>>((float*)d_out);
}